// round 1
// baseline (speedup 1.0000x reference)
#include <cuda_runtime.h>
#include <cstdint>

// Problem constants
#define BATCH 2
#define SEQ   2048
#define DMODEL 1024
#define NHEAD 16
#define HDIM  64
#define BH    (BATCH*NHEAD)          // 32
#define MROWS (BATCH*SEQ)            // 4096

// Scratch (device globals: allocation-free per harness rules)
__device__ float g_q[BH * SEQ * HDIM];     // [bh][s][hd]
__device__ float g_k[BH * SEQ * HDIM];
__device__ float g_v[BH * SEQ * HDIM];
__device__ float g_ctx[MROWS * DMODEL];    // [b*S+s][d]

// ---------------------------------------------------------------------------
// 128x128x16 fp32 SGEMM, 256 threads, 8x8 microtile.
// mode 0: C[row*N+col] = acc + bias[col]
// mode 1: scatter into g_q/g_k/g_v per QKV head layout (C unused)
// ---------------------------------------------------------------------------
__global__ __launch_bounds__(256) void gemm128(
    const float* __restrict__ A, const float* __restrict__ Bm,
    const float* __restrict__ bias, float* __restrict__ C,
    int M, int N, int K, int mode)
{
    __shared__ float As[128][20];   // [m][k], padded row (80B, float4-aligned)
    __shared__ float Bs[16][128];   // [k][n]

    const int tid = threadIdx.x;
    const int tx = tid & 15;
    const int ty = tid >> 4;
    const int m0 = blockIdx.y * 128;
    const int n0 = blockIdx.x * 128;

    float acc[8][8];
#pragma unroll
    for (int i = 0; i < 8; i++)
#pragma unroll
        for (int j = 0; j < 8; j++) acc[i][j] = 0.f;

    for (int kt = 0; kt < K; kt += 16) {
#pragma unroll
        for (int it = 0; it < 2; it++) {
            int f = tid + it * 256;           // 0..511
            int arow = f >> 2, akc = (f & 3) * 4;
            float4 av = *(const float4*)(A + (size_t)(m0 + arow) * K + kt + akc);
            *(float4*)&As[arow][akc] = av;
            int bkr = f >> 5, bnc = (f & 31) * 4;
            float4 bv = *(const float4*)(Bm + (size_t)(kt + bkr) * N + n0 + bnc);
            *(float4*)&Bs[bkr][bnc] = bv;
        }
        __syncthreads();
#pragma unroll
        for (int k = 0; k < 16; k++) {
            float a[8], b[8];
#pragma unroll
            for (int i = 0; i < 4; i++) {
                a[i]     = As[ty * 4 + i][k];
                a[i + 4] = As[64 + ty * 4 + i][k];
            }
            float4 b0 = *(float4*)&Bs[k][tx * 4];
            float4 b1 = *(float4*)&Bs[k][64 + tx * 4];
            b[0] = b0.x; b[1] = b0.y; b[2] = b0.z; b[3] = b0.w;
            b[4] = b1.x; b[5] = b1.y; b[6] = b1.z; b[7] = b1.w;
#pragma unroll
            for (int i = 0; i < 8; i++)
#pragma unroll
                for (int j = 0; j < 8; j++) acc[i][j] += a[i] * b[j];
        }
        __syncthreads();
    }

    // epilogue
#pragma unroll
    for (int i = 0; i < 8; i++) {
        int row = m0 + ((i < 4) ? (ty * 4 + i) : (64 + ty * 4 + (i - 4)));
#pragma unroll
        for (int jb = 0; jb < 2; jb++) {
            int col = n0 + tx * 4 + jb * 64;
            float4 v;
            v.x = acc[i][jb * 4 + 0] + bias[col + 0];
            v.y = acc[i][jb * 4 + 1] + bias[col + 1];
            v.z = acc[i][jb * 4 + 2] + bias[col + 2];
            v.w = acc[i][jb * 4 + 3] + bias[col + 3];
            if (mode == 0) {
                *(float4*)(C + (size_t)row * N + col) = v;
            } else {
                // col in [0,3072): part = col/1024 (q/k/v), h = (col%1024)/64, hd = col%64
                int part = col >> 10;
                int rr   = col & 1023;
                int h    = rr >> 6;
                int hd   = rr & 63;
                int bidx = row >> 11;          // row / SEQ
                int srow = row & 2047;         // row % SEQ
                float* dst = (part == 0) ? g_q : (part == 1) ? g_k : g_v;
                *(float4*)(dst + ((size_t)(bidx * NHEAD + h) * SEQ + srow) * HDIM + hd) = v;
            }
        }
    }
}

// ---------------------------------------------------------------------------
// Causal flash attention, fp32. One thread per query row.
// BM=128 rows/CTA, BN=32 keys/tile, HD=64. q/o/s in registers, K/V in smem.
// ---------------------------------------------------------------------------
__global__ __launch_bounds__(128) void attn_kernel()
{
    __shared__ float ks[32 * 64];
    __shared__ float vs[32 * 64];

    const int bh = blockIdx.y;
    const int m0 = blockIdx.x * 128;
    const int r  = m0 + threadIdx.x;     // query row (< SEQ)

    // load q row into registers
    float q[64];
    {
        const float4* qp = (const float4*)(g_q + ((size_t)bh * SEQ + r) * HDIM);
#pragma unroll
        for (int i = 0; i < 16; i++) ((float4*)q)[i] = qp[i];
    }

    float o[64];
#pragma unroll
    for (int d = 0; d < 64; d++) o[d] = 0.f;
    float mrun = -1e30f, lrun = 0.f;

    const int ntiles = (m0 + 128) / 32;   // causal: keys up to m0+127
    const float* kbase = g_k + (size_t)bh * SEQ * HDIM;
    const float* vbase = g_v + (size_t)bh * SEQ * HDIM;

    for (int t = 0; t < ntiles; t++) {
        const int kb = t * 32;
        __syncthreads();
#pragma unroll
        for (int i = 0; i < 4; i++) {
            int f = threadIdx.x + i * 128;   // 0..511 float4s (32*64 floats)
            ((float4*)ks)[f] = ((const float4*)(kbase + (size_t)kb * HDIM))[f];
            ((float4*)vs)[f] = ((const float4*)(vbase + (size_t)kb * HDIM))[f];
        }
        __syncthreads();

        float s[32];
#pragma unroll
        for (int j = 0; j < 32; j++) {
            float acc = 0.f;
#pragma unroll
            for (int d = 0; d < 64; d++) acc += q[d] * ks[j * 64 + d];
            s[j] = acc * 0.125f;   // 1/sqrt(64)
        }
        if (kb + 31 > r) {
#pragma unroll
            for (int j = 0; j < 32; j++)
                if (kb + j > r) s[j] = -1e30f;
        }

        float mt = mrun;
#pragma unroll
        for (int j = 0; j < 32; j++) mt = fmaxf(mt, s[j]);
        float alpha = __expf(mrun - mt);
        mrun = mt;

        float psum = 0.f;
#pragma unroll
        for (int j = 0; j < 32; j++) {
            s[j] = __expf(s[j] - mt);
            psum += s[j];
        }
        lrun = lrun * alpha + psum;

#pragma unroll
        for (int d = 0; d < 64; d++) o[d] *= alpha;
#pragma unroll
        for (int j = 0; j < 32; j++) {
            float pj = s[j];
#pragma unroll
            for (int d = 0; d < 64; d++) o[d] += pj * vs[j * 64 + d];
        }
    }

    const float inv = 1.f / lrun;
    const int bidx = bh >> 4;
    const int h    = bh & 15;
    float* op = g_ctx + ((size_t)(bidx * SEQ + r)) * DMODEL + h * HDIM;
#pragma unroll
    for (int i = 0; i < 16; i++) {
        float4 v4;
        v4.x = o[i * 4 + 0] * inv;
        v4.y = o[i * 4 + 1] * inv;
        v4.z = o[i * 4 + 2] * inv;
        v4.w = o[i * 4 + 3] * inv;
        ((float4*)op)[i] = v4;
    }
}

// ---------------------------------------------------------------------------
extern "C" void kernel_launch(void* const* d_in, const int* in_sizes, int n_in,
                              void* d_out, int out_size)
{
    const float* x      = (const float*)d_in[0];   // [B,S,D]
    const float* w_qkv  = (const float*)d_in[1];   // [D, 3D]
    const float* b_qkv  = (const float*)d_in[2];   // [3D]
    const float* w_proj = (const float*)d_in[3];   // [D, D]
    const float* b_proj = (const float*)d_in[4];   // [D]
    float* out = (float*)d_out;                    // [B,S,D]

    float* ctx;
    cudaGetSymbolAddress((void**)&ctx, g_ctx);

    // 1) QKV projection: [4096,1024] x [1024,3072] -> scatter to g_q/g_k/g_v
    {
        dim3 grid(3 * DMODEL / 128, MROWS / 128);  // (24, 32)
        gemm128<<<grid, 256>>>(x, w_qkv, b_qkv, nullptr,
                               MROWS, 3 * DMODEL, DMODEL, /*mode=*/1);
    }
    // 2) causal attention -> g_ctx
    {
        dim3 grid(SEQ / 128, BH);                  // (16, 32)
        attn_kernel<<<grid, 128>>>();
    }
    // 3) output projection: [4096,1024] x [1024,1024] -> d_out
    {
        dim3 grid(DMODEL / 128, MROWS / 128);      // (8, 32)
        gemm128<<<grid, 256>>>(ctx, w_proj, b_proj, out,
                               MROWS, DMODEL, DMODEL, /*mode=*/0);
    }
    (void)in_sizes; (void)n_in; (void)out_size;
}

// round 3
// speedup vs baseline: 3.3137x; 3.3137x over previous
#include <cuda_runtime.h>
#include <cstdint>

// Problem constants
#define BATCH 2
#define SEQ   2048
#define DMODEL 1024
#define NHEAD 16
#define HDIM  64
#define BH    (BATCH*NHEAD)          // 32
#define MROWS (BATCH*SEQ)            // 4096

// Scratch (device globals: allocation-free per harness rules)
__device__ float g_q[BH * SEQ * HDIM];     // [bh][s][hd]
__device__ float g_k[BH * SEQ * HDIM];
__device__ float g_v[BH * SEQ * HDIM];
__device__ float g_ctx[MROWS * DMODEL];    // [b*S+s][d]

// ---------------------------------------------------------------------------
// helpers
// ---------------------------------------------------------------------------
__device__ __forceinline__ uint32_t f2tf32(float x) {
    uint32_t r;
    asm("cvt.rna.tf32.f32 %0, %1;" : "=r"(r) : "f"(x));
    return r;
}

// mma.m16n8k8 tf32, D += A*B (C aliased to D)
__device__ __forceinline__ void mma8(float* d, const uint32_t* a, const uint32_t* b) {
    asm volatile(
        "mma.sync.aligned.m16n8k8.row.col.f32.tf32.tf32.f32 "
        "{%0,%1,%2,%3}, {%4,%5,%6,%7}, {%8,%9}, {%0,%1,%2,%3};\n"
        : "+f"(d[0]), "+f"(d[1]), "+f"(d[2]), "+f"(d[3])
        : "r"(a[0]), "r"(a[1]), "r"(a[2]), "r"(a[3]), "r"(b[0]), "r"(b[1]));
}

// fast 2^y for y <= 0 (clamped at -80), FMA-pipe only, rel err ~3e-6
__device__ __forceinline__ float exp2p(float y) {
    y = fmaxf(y, -80.f);
    int e = __float2int_rn(y);
    float f = y - (float)e;
    float p = 1.3333558e-3f;
    p = fmaf(p, f, 9.6181291e-3f);
    p = fmaf(p, f, 5.5504109e-2f);
    p = fmaf(p, f, 2.4022651e-1f);
    p = fmaf(p, f, 6.9314718e-1f);
    p = fmaf(p, f, 1.0f);
    return __int_as_float(__float_as_int(p) + (e << 23));
}

// ---------------------------------------------------------------------------
// tf32 mma.sync GEMM: C[M,N] = A[M,K] @ B[K,N] + bias.
// Tile 128x128x32, 256 threads, 8 warps as 2(m) x 4(n), warp tile 64x32.
// mode 0: write C ; mode 1: scatter into g_q/g_k/g_v (QKV head layout)
// ---------------------------------------------------------------------------
__global__ __launch_bounds__(256) void gemm_tc(
    const float* __restrict__ A, const float* __restrict__ Bm,
    const float* __restrict__ bias, float* __restrict__ C,
    int M, int N, int K, int mode)
{
    __shared__ float As[128 * 36];   // [m][k] pad 4
    __shared__ float Bs[32 * 132];   // [k][n] pad 4

    const int tid  = threadIdx.x;
    const int wid  = tid >> 5;
    const int lane = tid & 31;
    const int g = lane >> 2, t = lane & 3;
    const int wm = wid >> 2, wn = wid & 3;
    const int m0 = blockIdx.y * 128;
    const int n0 = blockIdx.x * 128;

    float acc[4][4][4];
#pragma unroll
    for (int mt = 0; mt < 4; mt++)
#pragma unroll
        for (int nt = 0; nt < 4; nt++)
#pragma unroll
            for (int j = 0; j < 4; j++) acc[mt][nt][j] = 0.f;

    for (int kt = 0; kt < K; kt += 32) {
        __syncthreads();
        // A tile [128 x 32]
#pragma unroll
        for (int i = 0; i < 4; i++) {
            int f = tid + i * 256;
            int row = f >> 3, c4 = (f & 7) * 4;
            float4 v = *(const float4*)(A + (size_t)(m0 + row) * K + kt + c4);
            uint4 u = { f2tf32(v.x), f2tf32(v.y), f2tf32(v.z), f2tf32(v.w) };
            *(uint4*)&As[row * 36 + c4] = u;
        }
        // B tile [32 x 128]
#pragma unroll
        for (int i = 0; i < 4; i++) {
            int f = tid + i * 256;
            int kr = f >> 5, nc4 = (f & 31) * 4;
            float4 v = *(const float4*)(Bm + (size_t)(kt + kr) * N + n0 + nc4);
            uint4 u = { f2tf32(v.x), f2tf32(v.y), f2tf32(v.z), f2tf32(v.w) };
            *(uint4*)&Bs[kr * 132 + nc4] = u;
        }
        __syncthreads();

#pragma unroll
        for (int ks = 0; ks < 4; ks++) {
            uint32_t bb[4][2];
#pragma unroll
            for (int nt = 0; nt < 4; nt++) {
                int col = wn * 32 + nt * 8 + g;
                bb[nt][0] = __float_as_uint(Bs[(ks * 8 + t) * 132 + col]);
                bb[nt][1] = __float_as_uint(Bs[(ks * 8 + t + 4) * 132 + col]);
            }
            uint32_t aa[4][4];
#pragma unroll
            for (int mt = 0; mt < 4; mt++) {
                int rb = wm * 64 + mt * 16;
                aa[mt][0] = __float_as_uint(As[(rb + g) * 36 + ks * 8 + t]);
                aa[mt][1] = __float_as_uint(As[(rb + g + 8) * 36 + ks * 8 + t]);
                aa[mt][2] = __float_as_uint(As[(rb + g) * 36 + ks * 8 + t + 4]);
                aa[mt][3] = __float_as_uint(As[(rb + g + 8) * 36 + ks * 8 + t + 4]);
            }
#pragma unroll
            for (int mt = 0; mt < 4; mt++)
#pragma unroll
                for (int nt = 0; nt < 4; nt++)
                    mma8(acc[mt][nt], aa[mt], bb[nt]);
        }
    }

    // epilogue: direct fragment stores (+bias)
#pragma unroll
    for (int mt = 0; mt < 4; mt++) {
        int r0 = m0 + wm * 64 + mt * 16 + g;
        int r1 = r0 + 8;
#pragma unroll
        for (int nt = 0; nt < 4; nt++) {
            int col = n0 + wn * 32 + nt * 8 + 2 * t;
            float2 b2 = *(const float2*)(bias + col);
            float2 v0 = { acc[mt][nt][0] + b2.x, acc[mt][nt][1] + b2.y };
            float2 v1 = { acc[mt][nt][2] + b2.x, acc[mt][nt][3] + b2.y };
            if (mode == 0) {
                *(float2*)(C + (size_t)r0 * N + col) = v0;
                *(float2*)(C + (size_t)r1 * N + col) = v1;
            } else {
                int part = col >> 10;
                int rr   = col & 1023;
                int h    = rr >> 6;
                int hd   = rr & 63;
                float* dst = (part == 0) ? g_q : (part == 1) ? g_k : g_v;
                int b0i = r0 >> 11, s0 = r0 & 2047;
                int b1i = r1 >> 11, s1 = r1 & 2047;
                *(float2*)(dst + ((size_t)(b0i * NHEAD + h) * SEQ + s0) * HDIM + hd) = v0;
                *(float2*)(dst + ((size_t)(b1i * NHEAD + h) * SEQ + s1) * HDIM + hd) = v1;
            }
        }
    }
}

// ---------------------------------------------------------------------------
// Tensor-core causal flash attention (tf32 mma.sync).
// CTA: 128 threads (4 warps), BM=64 query rows (16/warp), BN=64 keys/tile.
// smem: Qs (reused as P after Q-frag load) + Ks + Vs, each 64x68 f32.
// ---------------------------------------------------------------------------
#define ATT_SMEM (3 * 64 * 68 * 4)

__global__ __launch_bounds__(128) void attn_tc()
{
    extern __shared__ float smx[];
    float* Qs = smx;                 // 64x68 ; reused as P (16x68 per warp)
    float* Ks = smx + 64 * 68;
    float* Vs = smx + 2 * 64 * 68;

    const int tid  = threadIdx.x;
    const int wid  = tid >> 5;
    const int lane = tid & 31;
    const int g = lane >> 2, t = lane & 3;
    const int bh = blockIdx.y;
    const int m0 = blockIdx.x * 64;

    const float* qb = g_q + (size_t)bh * SEQ * HDIM;
    const float* kbp = g_k + (size_t)bh * SEQ * HDIM;
    const float* vbp = g_v + (size_t)bh * SEQ * HDIM;

    // stage Q tile (64x64) -> smem (tf32)
#pragma unroll
    for (int i = 0; i < 8; i++) {
        int f = tid + i * 128;
        int row = f >> 4, c4 = (f & 15) * 4;
        float4 v = *(const float4*)(qb + (size_t)(m0 + row) * HDIM + c4);
        uint4 u = { f2tf32(v.x), f2tf32(v.y), f2tf32(v.z), f2tf32(v.w) };
        *(uint4*)&Qs[row * 68 + c4] = u;
    }
    __syncthreads();

    // Q fragments: 8 k-steps x 4 regs
    uint32_t qa[8][4];
    {
        int rb = wid * 16;
#pragma unroll
        for (int ks = 0; ks < 8; ks++) {
            qa[ks][0] = __float_as_uint(Qs[(rb + g) * 68 + ks * 8 + t]);
            qa[ks][1] = __float_as_uint(Qs[(rb + g + 8) * 68 + ks * 8 + t]);
            qa[ks][2] = __float_as_uint(Qs[(rb + g) * 68 + ks * 8 + t + 4]);
            qa[ks][3] = __float_as_uint(Qs[(rb + g + 8) * 68 + ks * 8 + t + 4]);
        }
    }

    float o[8][4];
#pragma unroll
    for (int nt = 0; nt < 8; nt++)
#pragma unroll
        for (int j = 0; j < 4; j++) o[nt][j] = 0.f;
    float mlo = -1e30f, mhi = -1e30f, llo = 0.f, lhi = 0.f;

    const float SC = 0.125f * 1.44269504f;   // score scale in base-2 domain
    const int ntile = m0 / 64 + 1;

    for (int tt = 0; tt < ntile; tt++) {
        const int kb = tt * 64;
        __syncthreads();
        // load K,V tiles (64x64 each), tf32
#pragma unroll
        for (int i = 0; i < 8; i++) {
            int f = tid + i * 128;
            int row = f >> 4, c4 = (f & 15) * 4;
            float4 kv = *(const float4*)(kbp + (size_t)(kb + row) * HDIM + c4);
            uint4 uk = { f2tf32(kv.x), f2tf32(kv.y), f2tf32(kv.z), f2tf32(kv.w) };
            *(uint4*)&Ks[row * 68 + c4] = uk;
            float4 vv = *(const float4*)(vbp + (size_t)(kb + row) * HDIM + c4);
            uint4 uv = { f2tf32(vv.x), f2tf32(vv.y), f2tf32(vv.z), f2tf32(vv.w) };
            *(uint4*)&Vs[row * 68 + c4] = uv;
        }
        __syncthreads();

        // S = Q @ K^T  (warp: 16 x 64)
        float s[8][4];
#pragma unroll
        for (int nt = 0; nt < 8; nt++)
#pragma unroll
            for (int j = 0; j < 4; j++) s[nt][j] = 0.f;
#pragma unroll
        for (int ks = 0; ks < 8; ks++) {
#pragma unroll
            for (int nt = 0; nt < 8; nt++) {
                uint32_t bb[2];
                bb[0] = __float_as_uint(Ks[(nt * 8 + g) * 68 + ks * 8 + t]);
                bb[1] = __float_as_uint(Ks[(nt * 8 + g) * 68 + ks * 8 + t + 4]);
                mma8(s[nt], qa[ks], bb);
            }
        }

        // scale (+ causal mask on diagonal tile)
        const int rlo = m0 + wid * 16 + g;
        const int rhi = rlo + 8;
        if (kb == m0) {
#pragma unroll
            for (int nt = 0; nt < 8; nt++) {
                int c0 = kb + nt * 8 + 2 * t;
                s[nt][0] = (c0     > rlo) ? -1e30f : s[nt][0] * SC;
                s[nt][1] = (c0 + 1 > rlo) ? -1e30f : s[nt][1] * SC;
                s[nt][2] = (c0     > rhi) ? -1e30f : s[nt][2] * SC;
                s[nt][3] = (c0 + 1 > rhi) ? -1e30f : s[nt][3] * SC;
            }
        } else {
#pragma unroll
            for (int nt = 0; nt < 8; nt++)
#pragma unroll
                for (int j = 0; j < 4; j++) s[nt][j] *= SC;
        }

        // row max (quad reduction)
        float tlo = -1e30f, thi = -1e30f;
#pragma unroll
        for (int nt = 0; nt < 8; nt++) {
            tlo = fmaxf(tlo, fmaxf(s[nt][0], s[nt][1]));
            thi = fmaxf(thi, fmaxf(s[nt][2], s[nt][3]));
        }
        tlo = fmaxf(tlo, __shfl_xor_sync(0xffffffff, tlo, 1));
        tlo = fmaxf(tlo, __shfl_xor_sync(0xffffffff, tlo, 2));
        thi = fmaxf(thi, __shfl_xor_sync(0xffffffff, thi, 1));
        thi = fmaxf(thi, __shfl_xor_sync(0xffffffff, thi, 2));

        float nmlo = fmaxf(mlo, tlo), nmhi = fmaxf(mhi, thi);
        float alo = exp2p(mlo - nmlo), ahi = exp2p(mhi - nmhi);
        mlo = nmlo; mhi = nmhi;

        // p = 2^(s-m), partial sums
        float slo = 0.f, shi = 0.f;
#pragma unroll
        for (int nt = 0; nt < 8; nt++) {
            s[nt][0] = exp2p(s[nt][0] - mlo);
            s[nt][1] = exp2p(s[nt][1] - mlo);
            s[nt][2] = exp2p(s[nt][2] - mhi);
            s[nt][3] = exp2p(s[nt][3] - mhi);
            slo += s[nt][0] + s[nt][1];
            shi += s[nt][2] + s[nt][3];
        }
        slo += __shfl_xor_sync(0xffffffff, slo, 1);
        slo += __shfl_xor_sync(0xffffffff, slo, 2);
        shi += __shfl_xor_sync(0xffffffff, shi, 1);
        shi += __shfl_xor_sync(0xffffffff, shi, 2);
        llo = llo * alo + slo;
        lhi = lhi * ahi + shi;

        // rescale O
#pragma unroll
        for (int nt = 0; nt < 8; nt++) {
            o[nt][0] *= alo; o[nt][1] *= alo;
            o[nt][2] *= ahi; o[nt][3] *= ahi;
        }

        // P -> smem (warp-private 16x68 region), tf32
        float* Ps = Qs + wid * (16 * 68);
#pragma unroll
        for (int nt = 0; nt < 8; nt++) {
            int c = nt * 8 + 2 * t;
            uint2 plo = { f2tf32(s[nt][0]), f2tf32(s[nt][1]) };
            uint2 phi = { f2tf32(s[nt][2]), f2tf32(s[nt][3]) };
            *(uint2*)&Ps[g * 68 + c]       = plo;
            *(uint2*)&Ps[(g + 8) * 68 + c] = phi;
        }
        __syncwarp();

        // O += P @ V
#pragma unroll
        for (int ks = 0; ks < 8; ks++) {
            uint32_t aa[4];
            aa[0] = __float_as_uint(Ps[g * 68 + ks * 8 + t]);
            aa[1] = __float_as_uint(Ps[(g + 8) * 68 + ks * 8 + t]);
            aa[2] = __float_as_uint(Ps[g * 68 + ks * 8 + t + 4]);
            aa[3] = __float_as_uint(Ps[(g + 8) * 68 + ks * 8 + t + 4]);
#pragma unroll
            for (int nt = 0; nt < 8; nt++) {
                uint32_t bb[2];
                bb[0] = __float_as_uint(Vs[(ks * 8 + t) * 68 + nt * 8 + g]);
                bb[1] = __float_as_uint(Vs[(ks * 8 + t + 4) * 68 + nt * 8 + g]);
                mma8(o[nt], aa, bb);
            }
        }
        __syncwarp();
    }

    // epilogue: O /= l, write to ctx
    const float ilo = 1.f / llo, ihi = 1.f / lhi;
    const int rlo = m0 + wid * 16 + g;
    const int rhi = rlo + 8;
    const int bidx = bh >> 4, h = bh & 15;
    float* clo = g_ctx + ((size_t)(bidx * SEQ + rlo)) * DMODEL + h * HDIM;
    float* chi = g_ctx + ((size_t)(bidx * SEQ + rhi)) * DMODEL + h * HDIM;
#pragma unroll
    for (int nt = 0; nt < 8; nt++) {
        int c = nt * 8 + 2 * t;
        float2 v0 = { o[nt][0] * ilo, o[nt][1] * ilo };
        float2 v1 = { o[nt][2] * ihi, o[nt][3] * ihi };
        *(float2*)(clo + c) = v0;
        *(float2*)(chi + c) = v1;
    }
}

// ---------------------------------------------------------------------------
extern "C" void kernel_launch(void* const* d_in, const int* in_sizes, int n_in,
                              void* d_out, int out_size)
{
    const float* x      = (const float*)d_in[0];   // [B,S,D]
    const float* w_qkv  = (const float*)d_in[1];   // [D, 3D]
    const float* b_qkv  = (const float*)d_in[2];   // [3D]
    const float* w_proj = (const float*)d_in[3];   // [D, D]
    const float* b_proj = (const float*)d_in[4];   // [D]
    float* out = (float*)d_out;                    // [B,S,D]

    float* ctx;
    cudaGetSymbolAddress((void**)&ctx, g_ctx);

    cudaFuncSetAttribute(attn_tc, cudaFuncAttributeMaxDynamicSharedMemorySize, ATT_SMEM);

    // 1) QKV projection -> g_q/g_k/g_v
    {
        dim3 grid(3 * DMODEL / 128, MROWS / 128);  // (24, 32)
        gemm_tc<<<grid, 256>>>(x, w_qkv, b_qkv, nullptr,
                               MROWS, 3 * DMODEL, DMODEL, /*mode=*/1);
    }
    // 2) causal attention -> g_ctx
    {
        dim3 grid(SEQ / 64, BH);                   // (32, 32)
        attn_tc<<<grid, 128, ATT_SMEM>>>();
    }
    // 3) output projection -> d_out
    {
        dim3 grid(DMODEL / 128, MROWS / 128);      // (8, 32)
        gemm_tc<<<grid, 256>>>(ctx, w_proj, b_proj, out,
                               MROWS, DMODEL, DMODEL, /*mode=*/0);
    }
    (void)in_sizes; (void)n_in; (void)out_size;
}